// round 6
// baseline (speedup 1.0000x reference)
#include <cuda_runtime.h>
#include <math.h>

#define Bc      8
#define Nc      1024
#define NTYPESc 2
#define MNc     128
#define Mc      256          // NTYPES*MN
#define BETAc   8
#define M1c     16
#define M2c     4
#define NFEATc  64           // M1*M2
#define Hc      128
#define NGHOSTc 64
#define NTOT    (Nc + NGHOSTc)   // 1088
#define RMAXc   6.0f
#define RMINc   0.5f
#define SPANc   5.5f
#define PI_F    3.14159265358979323846f

#define O_ETOT  0
#define O_EI    (O_ETOT + Bc)                 // 8
#define O_FORCE (O_EI + Bc*Nc)                // 8200
#define O_VIR   (O_FORCE + Bc*NTOT*3)         // 34312
#define OUT_TOTAL (O_VIR + Bc*9)              // 34384

typedef unsigned long long u64;

// ---------------- packed f32x2 helpers ----------------
__device__ __forceinline__ u64 pk2(float lo, float hi) {
    u64 r; asm("mov.b64 %0, {%1, %2};" : "=l"(r) : "f"(lo), "f"(hi)); return r;
}
__device__ __forceinline__ void upk2(u64 v, float& lo, float& hi) {
    asm("mov.b64 {%0, %1}, %2;" : "=f"(lo), "=f"(hi) : "l"(v));
}
__device__ __forceinline__ u64 ffma2(u64 a, u64 b, u64 c) {
    u64 d; asm("fma.rn.f32x2 %0, %1, %2, %3;" : "=l"(d) : "l"(a), "l"(b), "l"(c)); return d;
}

// ---------------- device scratch (no allocation allowed) ----------------
__device__ float  g_S    [Bc*Nc*NFEATc];   // S (B,N,16,4), already /M
__device__ float  g_feat [Bc*Nc*NFEATc];   // raw features
__device__ float  g_dfeat[Bc*Nc*NFEATc];   // dE/dfeat_raw (incl. 1/std)
__device__ double g_sum  [NTYPESc];
__device__ double g_sumsq[NTYPESc];
__device__ float  g_mu   [NTYPESc];
__device__ float  g_istd [NTYPESc];        // 1/std
__device__ float  g_W0T  [NTYPESc*Hc*NFEATc];  // [t][j][p]
__device__ float  g_W1T  [NTYPESc*Hc*Hc];      // [t][j][i]
__device__ float  g_W2T  [NTYPESc*Hc*Hc];

__device__ __forceinline__ float wsum(float v) {
    v += __shfl_xor_sync(0xffffffffu, v, 16);
    v += __shfl_xor_sync(0xffffffffu, v, 8);
    v += __shfl_xor_sync(0xffffffffu, v, 4);
    v += __shfl_xor_sync(0xffffffffu, v, 2);
    v += __shfl_xor_sync(0xffffffffu, v, 1);
    return v;
}

// packed butterfly step: 2*HALF values -> HALF, component bit taken from lane bit OFF
template<int HALF, int OFF>
__device__ __forceinline__ void bstep(float* v, int lane) {
    bool hi = (lane & OFF) != 0;
#pragma unroll
    for (int i = 0; i < HALF; i++) {
        float send = hi ? v[i] : v[i + HALF];
        float recv = __shfl_xor_sync(0xffffffffu, send, OFF);
        v[i] = (hi ? v[i + HALF] : v[i]) + recv;
    }
}

// ---------------- kernel 0: zero outputs + transpose weights -------------
__global__ void prep_kernel(float* out,
                            const float* __restrict__ W0,
                            const float* __restrict__ W1,
                            const float* __restrict__ W2) {
    int i = blockIdx.x * blockDim.x + threadIdx.x;
    if (i < OUT_TOTAL) out[i] = 0.0f;
    if (i < NTYPESc) { g_sum[i] = 0.0; g_sumsq[i] = 0.0; }
    if (i < NTYPESc*Hc*NFEATc) {
        int t = i / (Hc*NFEATc); int r = i % (Hc*NFEATc);
        int j = r / NFEATc;      int p = r % NFEATc;
        g_W0T[i] = W0[(t*NFEATc + p)*Hc + j];
    }
    if (i < NTYPESc*Hc*Hc) {
        int t = i / (Hc*Hc); int r = i % (Hc*Hc);
        int j = r / Hc;      int k = r % Hc;
        g_W1T[i] = W1[(t*Hc + k)*Hc + j];
        g_W2T[i] = W2[(t*Hc + k)*Hc + j];
    }
}

// ---------------- kernel 2: features + per-type stats --------------------
// block = 2 atoms x 128 threads; each thread handles 2 neighbors
__global__ void feat_kernel(const float* __restrict__ rvec,
                            const int*   __restrict__ tmap,
                            const float* __restrict__ cparam) {
    int bn0 = blockIdx.x * 2;
    int n0  = bn0 & (Nc - 1);
    int tid = threadIdx.x;           // 0..255
    int half = tid >> 7;             // which atom of the pair
    int t    = tid & 127;            // per-atom thread
    int bn   = bn0 + half;
    int ti   = tmap[n0];             // pair shares type (sorted map, pairs don't straddle)

    __shared__ __align__(16) float ct[NTYPESc*BETAc*M1c];  // [tj][k][p]
    __shared__ float S_sh[2][NFEATc];
    __shared__ float Sn[2][NFEATc];
    __shared__ float ps[8], ps2[8];

    {   // load c transposed: source index tid = tj*128 + p*8 + k
        int tjl = tid >> 7, rem = tid & 127, p = rem >> 3, k = rem & 7;
        ct[tjl*128 + k*16 + p] = cparam[ti * (NTYPESc*M1c*BETAc) + tid];
    }
    if (t < NFEATc) S_sh[half][t] = 0.0f;
    __syncthreads();

    int tj = t >> 6;                 // neighbors 2t,2t+1 share tj
    const u64* cp = (const u64*)(ct + tj * 128);

    float v[NFEATc];
#pragma unroll
    for (int i = 0; i < NFEATc; i++) v[i] = 0.0f;

#pragma unroll
    for (int s = 0; s < 2; s++) {
        int m = 2*t + s;
        const float* rv = rvec + ((long)bn * Mc + m) * 3;
        float x = rv[0], y = rv[1], z = rv[2];
        float r2 = x*x + y*y + z*z;
        bool  valid = r2 > 1e-12f;
        float rinv0 = rsqrtf(fmaxf(r2, 1e-30f));
        float rs  = valid ? r2 * rinv0 : 1.0f;
        float inv = valid ? rinv0 : 1.0f;
        float u = 2.0f*(rs - RMINc)/SPANc - 1.0f;
        u = fminf(fmaxf(u, -1.0f), 1.0f);
        float rc = fminf(fmaxf(rs, RMINc), RMAXc);
        float fc = (valid && rs < RMAXc)
                 ? 0.5f*(__cosf(PI_F*(rc - RMINc)/SPANc) + 1.0f) : 0.0f;

        float T[BETAc];
        T[0] = 1.0f; T[1] = u;
#pragma unroll
        for (int k = 2; k < BETAc; k++) T[k] = 2.0f*u*T[k-1] - T[k-2];
        u64 Td[BETAc];
#pragma unroll
        for (int k = 0; k < BETAc; k++) Td[k] = pk2(T[k], T[k]);

        float q0 = valid ? 1.0f : 0.0f;
        float qv[4]; qv[0] = q0; qv[1] = x*inv*q0; qv[2] = y*inv*q0; qv[3] = z*inv*q0;

        u64 P2[8];
#pragma unroll
        for (int pp = 0; pp < 8; pp++) P2[pp] = 0ULL;
#pragma unroll
        for (int k = 0; k < BETAc; k++)
#pragma unroll
            for (int pp = 0; pp < 8; pp++) P2[pp] = ffma2(cp[k*8 + pp], Td[k], P2[pp]);

#pragma unroll
        for (int pp = 0; pp < 8; pp++) {
            float a, b; upk2(P2[pp], a, b);
            float g0 = a * fc, g1 = b * fc;
            int p0 = 2*pp, p1 = 2*pp + 1;
            v[p0*4+0] += g0*qv[0]; v[p0*4+1] += g0*qv[1];
            v[p0*4+2] += g0*qv[2]; v[p0*4+3] += g0*qv[3];
            v[p1*4+0] += g1*qv[0]; v[p1*4+1] += g1*qv[1];
            v[p1*4+2] += g1*qv[2]; v[p1*4+3] += g1*qv[3];
        }
    }

    int lane = tid & 31;
    bstep<32, 16>(v, lane);
    bstep<16,  8>(v, lane);
    bstep< 8,  4>(v, lane);
    bstep< 4,  2>(v, lane);
    bstep< 2,  1>(v, lane);
    atomicAdd(&S_sh[half][2*lane + 0], v[0]);
    atomicAdd(&S_sh[half][2*lane + 1], v[1]);
    __syncthreads();

    if (t < NFEATc) {
        float s = S_sh[half][t] * (1.0f / Mc);
        Sn[half][t] = s;
        g_S[(long)bn * NFEATc + t] = s;
    }
    __syncthreads();

    float f = 0.0f;
    if (t < NFEATc) {
        int p = t >> 2, qi = t & 3;
#pragma unroll
        for (int a = 0; a < 4; a++) f += Sn[half][p*4 + a] * Sn[half][qi*4 + a];
        g_feat[(long)bn * NFEATc + t] = f;
    }
    float fs  = wsum(f);
    float f2s = wsum(f * f);
    if (lane == 0) { ps[tid >> 5] = fs; ps2[tid >> 5] = f2s; }
    __syncthreads();
    if (tid == 0) {
        float s = 0.0f, s2 = 0.0f;
#pragma unroll
        for (int w = 0; w < 8; w++) { s += ps[w]; s2 += ps2[w]; }
        atomicAdd(&g_sum[ti],  (double)s);
        atomicAdd(&g_sumsq[ti], (double)s2);
    }
}

// ---------------- kernel 3: finalize stats (warp-reduced counting) -------
__global__ void stats_kernel(const int* __restrict__ tmap) {
    __shared__ float wcnt[8];
    int tid = threadIdx.x;
    float c0 = 0.0f;
    for (int i = tid; i < Nc; i += 256) c0 += (tmap[i] == 0) ? 1.0f : 0.0f;
    c0 = wsum(c0);
    if ((tid & 31) == 0) wcnt[tid >> 5] = c0;
    __syncthreads();
    if (tid == 0) {
        float n0 = 0.0f;
#pragma unroll
        for (int w = 0; w < 8; w++) n0 += wcnt[w];
        int cnt[NTYPESc];
        cnt[0] = (int)(n0 + 0.5f);
        cnt[1] = Nc - cnt[0];
        for (int t = 0; t < NTYPESc; t++) {
            double c   = (double)cnt[t] * Bc * NFEATc;
            double mu  = g_sum[t] / c;
            double var = (g_sumsq[t] - g_sum[t]*g_sum[t]/c) / (c - 1.0);
            g_mu[t]   = (float)mu;
            g_istd[t] = (float)(1.0 / sqrt(var));
        }
    }
}

// ---------------- kernel 4: MLP fwd+bwd, warp-per-2-atoms, FFMA2 ---------
__device__ __forceinline__ void fma4x2(u64 (&z)[4], float4 wv, float2 xv) {
    u64 x01 = pk2(xv.x, xv.y);
    z[0] = ffma2(pk2(wv.x, wv.x), x01, z[0]);
    z[1] = ffma2(pk2(wv.y, wv.y), x01, z[1]);
    z[2] = ffma2(pk2(wv.z, wv.z), x01, z[2]);
    z[3] = ffma2(pk2(wv.w, wv.w), x01, z[3]);
}

#define MLP_WARPS 4
#define APW 2
__global__ void __launch_bounds__(128) mlp_kernel(
        const int* __restrict__ tmap,
        const float* __restrict__ W0, const float* __restrict__ b0,
        const float* __restrict__ W1, const float* __restrict__ b1,
        const float* __restrict__ W2, const float* __restrict__ b2,
        const float* __restrict__ Wout, const float* __restrict__ bout,
        float* __restrict__ outEi, float* __restrict__ outEtot) {
    __shared__ float2 bufA[MLP_WARPS][Hc];
    __shared__ float2 bufB[MLP_WARPS][Hc];

    const int w   = threadIdx.x >> 5;
    const int ln  = threadIdx.x & 31;
    const int bn0 = (blockIdx.x * MLP_WARPS + w) * APW;
    const int n0  = bn0 & (Nc - 1);
    const int b   = bn0 >> 10;
    const int t   = tmap[n0];
    const float mu = g_mu[t], istd = g_istd[t];

    float*        Af = (float*)bufA[w];
    const float2* A2 = bufA[w];
    const float2* B2 = bufB[w];

#pragma unroll
    for (int k = 0; k < 4; k++) {
        int idx = k * 32 + ln;
        int p = idx >> 1, a = idx & 1;
        Af[idx] = (g_feat[(size_t)(bn0 + a) * NFEATc + p] - mu) * istd;
    }
    __syncwarp();

    const float4* W0f  = (const float4*)(W0    + (size_t)t * NFEATc * Hc);
    const float4* W1f  = (const float4*)(W1    + (size_t)t * Hc * Hc);
    const float4* W2f  = (const float4*)(W2    + (size_t)t * Hc * Hc);
    const float4* W1Tf = (const float4*)(g_W1T + (size_t)t * Hc * Hc);
    const float4* W2Tf = (const float4*)(g_W2T + (size_t)t * Hc * Hc);
    const float2* W0T2 = (const float2*)(g_W0T + (size_t)t * Hc * NFEATc);

    u64 acc2[4];
    float a0r[8], a1r[8], a2r[8], h1r[8];

    // ---- layer 0 ----
    {
        float4 bb = ((const float4*)(b0 + t * Hc))[ln];
        acc2[0] = pk2(bb.x, bb.x);
        acc2[1] = pk2(bb.y, bb.y);
        acc2[2] = pk2(bb.z, bb.z);
        acc2[3] = pk2(bb.w, bb.w);
    }
#pragma unroll 8
    for (int p = 0; p < NFEATc; p++) fma4x2(acc2, W0f[p*32 + ln], A2[p]);
#pragma unroll
    for (int o = 0; o < 4; o++) {
        float u0_, u1_;
        upk2(acc2[o], u0_, u1_);
        a0r[o*2+0] = tanhf(u0_); a0r[o*2+1] = tanhf(u1_);
    }
#pragma unroll
    for (int o = 0; o < 4; o++)
        bufB[w][4*ln + o] = make_float2(a0r[o*2+0], a0r[o*2+1]);
    __syncwarp();

    // ---- layer 1 ----
    {
        float4 bb = ((const float4*)(b1 + t * Hc))[ln];
        acc2[0] = pk2(bb.x, bb.x);
        acc2[1] = pk2(bb.y, bb.y);
        acc2[2] = pk2(bb.z, bb.z);
        acc2[3] = pk2(bb.w, bb.w);
    }
#pragma unroll 8
    for (int p = 0; p < Hc; p++) fma4x2(acc2, W1f[p*32 + ln], B2[p]);
#pragma unroll
    for (int o = 0; o < 4; o++) {
        float u0_, u1_;
        upk2(acc2[o], u0_, u1_);
        a1r[o*2+0] = tanhf(u0_); a1r[o*2+1] = tanhf(u1_);
    }
#pragma unroll
    for (int i = 0; i < 8; i++) h1r[i] = a1r[i] + a0r[i];
#pragma unroll
    for (int o = 0; o < 4; o++)
        bufA[w][4*ln + o] = make_float2(h1r[o*2+0], h1r[o*2+1]);
    __syncwarp();

    // ---- layer 2 ----
    {
        float4 bb = ((const float4*)(b2 + t * Hc))[ln];
        acc2[0] = pk2(bb.x, bb.x);
        acc2[1] = pk2(bb.y, bb.y);
        acc2[2] = pk2(bb.z, bb.z);
        acc2[3] = pk2(bb.w, bb.w);
    }
#pragma unroll 8
    for (int p = 0; p < Hc; p++) fma4x2(acc2, W2f[p*32 + ln], A2[p]);
#pragma unroll
    for (int o = 0; o < 4; o++) {
        float u0_, u1_;
        upk2(acc2[o], u0_, u1_);
        a2r[o*2+0] = tanhf(u0_); a2r[o*2+1] = tanhf(u1_);
    }

    // ---- energy ----
    float4 wo = ((const float4*)(Wout + t * Hc))[ln];
    float e0, e1;
    {
        float h2[8];
#pragma unroll
        for (int i = 0; i < 8; i++) h2[i] = a2r[i] + h1r[i];
        e0 = wo.x*h2[0] + wo.y*h2[2] + wo.z*h2[4] + wo.w*h2[6];
        e1 = wo.x*h2[1] + wo.y*h2[3] + wo.z*h2[5] + wo.w*h2[7];
    }
    e0 = wsum(e0); e1 = wsum(e1);
    float bo = bout[t];
    if (ln < 2) outEi[bn0 + ln] = ((ln == 0) ? e0 : e1) + bo;
    if (ln == 0) atomicAdd(&outEtot[b], e0 + e1 + 2.0f * bo);

    // ---- backward ----
#pragma unroll
    for (int o = 0; o < 4; o++) {
        float wc = (o == 0) ? wo.x : (o == 1) ? wo.y : (o == 2) ? wo.z : wo.w;
        bufB[w][4*ln + o] = make_float2(wc * (1.0f - a2r[o*2+0]*a2r[o*2+0]),
                                        wc * (1.0f - a2r[o*2+1]*a2r[o*2+1]));
    }
    __syncwarp();

    u64 dh2[4];
    dh2[0] = pk2(wo.x, wo.x);
    dh2[1] = pk2(wo.y, wo.y);
    dh2[2] = pk2(wo.z, wo.z);
    dh2[3] = pk2(wo.w, wo.w);
#pragma unroll 8
    for (int j = 0; j < Hc; j++) fma4x2(dh2, W2Tf[j*32 + ln], B2[j]);

#pragma unroll
    for (int o = 0; o < 4; o++) {
        float d0, d1;
        upk2(dh2[o], d0, d1);
        bufA[w][4*ln + o] = make_float2(d0 * (1.0f - a1r[o*2+0]*a1r[o*2+0]),
                                        d1 * (1.0f - a1r[o*2+1]*a1r[o*2+1]));
    }
    __syncwarp();

#pragma unroll 8
    for (int j = 0; j < Hc; j++) fma4x2(dh2, W1Tf[j*32 + ln], A2[j]);

#pragma unroll
    for (int o = 0; o < 4; o++) {
        float d0, d1;
        upk2(dh2[o], d0, d1);
        bufB[w][4*ln + o] = make_float2(d0 * (1.0f - a0r[o*2+0]*a0r[o*2+0]),
                                        d1 * (1.0f - a0r[o*2+1]*a0r[o*2+1]));
    }
    __syncwarp();

    u64 dx0p = 0ULL, dx1p = 0ULL;
#pragma unroll 8
    for (int j = 0; j < Hc; j++) {
        float2 w2 = W0T2[j*32 + ln];
        float2 vv = B2[j];
        u64 v01 = pk2(vv.x, vv.y);
        dx0p = ffma2(pk2(w2.x, w2.x), v01, dx0p);
        dx1p = ffma2(pk2(w2.y, w2.y), v01, dx1p);
    }
    float dx0a, dx0b, dx1a, dx1b;
    upk2(dx0p, dx0a, dx0b);
    upk2(dx1p, dx1a, dx1b);
    ((float2*)g_dfeat)[(size_t)(bn0 + 0) * (NFEATc/2) + ln] =
        make_float2(dx0a * istd, dx1a * istd);
    ((float2*)g_dfeat)[(size_t)(bn0 + 1) * (NFEATc/2) + ln] =
        make_float2(dx0b * istd, dx1b * istd);
}

// ---------------- kernel 5: gradient w.r.t. rvec, forces, virial ----------
__global__ void grad_kernel(const float* __restrict__ rvec,
                            const int*   __restrict__ tmap,
                            const float* __restrict__ cparam,
                            const int*   __restrict__ list_neigh,
                            float* __restrict__ Force,
                            float* __restrict__ Virial) {
    int bn = blockIdx.x;
    int n  = bn & (Nc - 1);
    int b  = bn >> 10;
    int m  = threadIdx.x;
    int ti = tmap[n];

    __shared__ __align__(16) float ct[NTYPESc*BETAc*M1c];  // [tj][k][p]
    __shared__ float dfs[NFEATc], Ss[NFEATc];
    __shared__ __align__(16) float dsT[4*M1c];             // [a][p]
    __shared__ float acc[12];

    {
        int tjl = m >> 7, rem = m & 127, p = rem >> 3, k = rem & 7;
        ct[tjl*128 + k*16 + p] = cparam[ti * (NTYPESc*M1c*BETAc) + m];
    }
    if (m < NFEATc) {
        dfs[m] = g_dfeat[(long)bn*NFEATc + m];
        Ss[m]  = g_S[(long)bn*NFEATc + m];
    }
    if (m < 12) acc[m] = 0.0f;
    __syncthreads();

    if (m < NFEATc) {
        int r = m >> 2, a = m & 3;
        float v = 0.0f;
#pragma unroll
        for (int q = 0; q < 4; q++) v += dfs[r*4 + q] * Ss[q*4 + a];
        if (r < 4) {
#pragma unroll
            for (int p = 0; p < M1c; p++) v += dfs[p*4 + r] * Ss[p*4 + a];
        }
        dsT[a*M1c + r] = v;
    }
    __syncthreads();

    const float* rv = rvec + ((long)bn * Mc + m) * 3;
    float x = rv[0], y = rv[1], z = rv[2];
    float r2 = x*x + y*y + z*z;
    bool  valid = r2 > 1e-12f;
    float rinv0 = rsqrtf(fmaxf(r2, 1e-30f));
    float rs  = valid ? r2 * rinv0 : 1.0f;
    float inv = valid ? rinv0 : 1.0f;
    float ux = x*inv, uy = y*inv, uz = z*inv;

    float u0 = 2.0f*(rs - RMINc)/SPANc - 1.0f;
    bool  uin = (u0 > -1.0f) && (u0 < 1.0f);
    float u = fminf(fmaxf(u0, -1.0f), 1.0f);
    float rc = fminf(fmaxf(rs, RMINc), RMAXc);
    float arg = PI_F*(rc - RMINc)/SPANc;
    float fc = (valid && rs < RMAXc) ? 0.5f*(__cosf(arg) + 1.0f) : 0.0f;
    float dfc_dr = (valid && rs < RMAXc && rs > RMINc)
                 ? -0.5f*PI_F/SPANc*__sinf(arg) : 0.0f;
    float du_dr  = uin ? 2.0f/SPANc : 0.0f;

    float T[BETAc], D[BETAc];
    T[0] = 1.0f; T[1] = u; D[0] = 0.0f; D[1] = 1.0f;
#pragma unroll
    for (int k = 2; k < BETAc; k++) {
        T[k] = 2.0f*u*T[k-1] - T[k-2];
        D[k] = 2.0f*T[k-1] + 2.0f*u*D[k-1] - D[k-2];
    }
    u64 Td[BETAc], Dd[BETAc];
#pragma unroll
    for (int k = 0; k < BETAc; k++) { Td[k] = pk2(T[k], T[k]); Dd[k] = pk2(D[k], D[k]); }

    int tj = m >> 7;
    const u64* cp  = (const u64*)(ct + tj * 128);
    const u64* ds0 = (const u64*)dsT;
    float q0 = valid ? 1.0f : 0.0f;
    float qv[4]; qv[0] = q0; qv[1] = ux*q0; qv[2] = uy*q0; qv[3] = uz*q0;

    u64 P2[8], Pd2[8];
#pragma unroll
    for (int pp = 0; pp < 8; pp++) { P2[pp] = 0ULL; Pd2[pp] = 0ULL; }
#pragma unroll
    for (int k = 0; k < BETAc; k++) {
#pragma unroll
        for (int pp = 0; pp < 8; pp++) {
            u64 c2 = cp[k*8 + pp];
            P2[pp]  = ffma2(c2, Td[k], P2[pp]);
            Pd2[pp] = ffma2(c2, Dd[k], Pd2[pp]);
        }
    }

    u64 dg2[8];
#pragma unroll
    for (int pp = 0; pp < 8; pp++) dg2[pp] = 0ULL;
#pragma unroll
    for (int a = 0; a < 4; a++) {
        u64 qd = pk2(qv[a], qv[a]);
#pragma unroll
        for (int pp = 0; pp < 8; pp++) dg2[pp] = ffma2(ds0[a*8 + pp], qd, dg2[pp]);
    }

    u64 f2 = 0ULL, up2 = 0ULL, x2 = 0ULL, y2 = 0ULL, z2 = 0ULL;
#pragma unroll
    for (int pp = 0; pp < 8; pp++) {
        f2  = ffma2(dg2[pp], P2[pp],  f2);
        up2 = ffma2(dg2[pp], Pd2[pp], up2);
        x2  = ffma2(ds0[ 8 + pp], P2[pp], x2);
        y2  = ffma2(ds0[16 + pp], P2[pp], y2);
        z2  = ffma2(ds0[24 + pp], P2[pp], z2);
    }
    const float invM = 1.0f / Mc;
    float lo_, hi_;
    upk2(f2,  lo_, hi_); float dfc = (lo_ + hi_) * invM;
    upk2(up2, lo_, hi_); float duP = (lo_ + hi_) * invM;
    upk2(x2,  lo_, hi_); float dux = (lo_ + hi_) * invM * fc * q0;
    upk2(y2,  lo_, hi_); float duy = (lo_ + hi_) * invM * fc * q0;
    upk2(z2,  lo_, hi_); float duz = (lo_ + hi_) * invM * fc * q0;

    float du  = fc * duP;
    float drs = dfc * dfc_dr + du * du_dr;
    float dot = dux*ux + duy*uy + duz*uz;

    float fx = 0.0f, fy = 0.0f, fz = 0.0f;
    if (valid) {
        fx = drs*ux + (dux - dot*ux)*inv;
        fy = drs*uy + (duy - dot*uy)*inv;
        fz = drs*uz + (duz - dot*uz)*inv;
    }

    int nb = list_neigh[(long)bn * Mc + m];
    if (nb > 0) {
        long fj = ((long)b * NTOT + (nb - 1)) * 3;
        atomicAdd(&Force[fj + 0], -fx);
        atomicAdd(&Force[fj + 1], -fy);
        atomicAdd(&Force[fj + 2], -fz);
    }

    // center force + virial: packed butterfly over 16 components.
    // Steps OFF=16,8,4,2 reduce over lane bits 4..1; final OFF=1 add combines
    // the remaining parity (lane bit 0) so every lane holds the FULL sum of
    // component ((lane>>1)&15). (Round-5 bug: this last step was missing.)
    int lane = m & 31;
    float vals[16];
    vals[0] = fx;   vals[1] = fy;   vals[2] = fz;
    vals[3]  = x*fx; vals[4]  = x*fy; vals[5]  = x*fz;
    vals[6]  = y*fx; vals[7]  = y*fy; vals[8]  = y*fz;
    vals[9]  = z*fx; vals[10] = z*fy; vals[11] = z*fz;
    vals[12] = vals[13] = vals[14] = vals[15] = 0.0f;
    bstep<8, 16>(vals, lane);
    bstep<4,  8>(vals, lane);
    bstep<2,  4>(vals, lane);
    bstep<1,  2>(vals, lane);
    vals[0] += __shfl_xor_sync(0xffffffffu, vals[0], 1);
    if ((lane & 1) == 0) {
        int c = (lane >> 1) & 15;
        if (c < 12) atomicAdd(&acc[c], vals[0]);
    }
    __syncthreads();
    if (m < 3)  atomicAdd(&Force[((long)b*NTOT + n)*3 + m], acc[m]);
    if (m >= 3 && m < 12) atomicAdd(&Virial[b*9 + (m - 3)], -acc[m]);
}

// ---------------- launch ---------------------------------------------------
extern "C" void kernel_launch(void* const* d_in, const int* in_sizes, int n_in,
                              void* d_out, int out_size) {
    const int*   list_neigh = (const int*)  d_in[0];
    const int*   tmap       = (const int*)  d_in[1];
    const float* rvec       = (const float*)d_in[2];
    const float* cparam     = (const float*)d_in[3];
    const float* W0         = (const float*)d_in[4];
    const float* b0         = (const float*)d_in[5];
    const float* W1         = (const float*)d_in[6];
    const float* b1         = (const float*)d_in[7];
    const float* W2         = (const float*)d_in[8];
    const float* b2         = (const float*)d_in[9];
    const float* Wout       = (const float*)d_in[10];
    const float* bout       = (const float*)d_in[11];

    float* out      = (float*)d_out;
    float* outEtot  = out + O_ETOT;
    float* outEi    = out + O_EI;
    float* outForce = out + O_FORCE;
    float* outVir   = out + O_VIR;

    prep_kernel<<<(OUT_TOTAL + 255) / 256, 256>>>(out, W0, W1, W2);
    feat_kernel<<<Bc*Nc/2, 256>>>(rvec, tmap, cparam);
    stats_kernel<<<1, 256>>>(tmap);
    mlp_kernel<<<Bc*Nc / (MLP_WARPS*APW), 128>>>(tmap, W0, b0, W1, b1, W2, b2,
                                                 Wout, bout, outEi, outEtot);
    grad_kernel<<<Bc*Nc, 256>>>(rvec, tmap, cparam, list_neigh, outForce, outVir);
}

// round 7
// speedup vs baseline: 1.0753x; 1.0753x over previous
#include <cuda_runtime.h>
#include <math.h>

#define Bc      8
#define Nc      1024
#define NTYPESc 2
#define MNc     128
#define Mc      256          // NTYPES*MN
#define BETAc   8
#define M1c     16
#define M2c     4
#define NFEATc  64           // M1*M2
#define Hc      128
#define NGHOSTc 64
#define NTOT    (Nc + NGHOSTc)   // 1088
#define RMAXc   6.0f
#define RMINc   0.5f
#define SPANc   5.5f
#define PI_F    3.14159265358979323846f

#define O_ETOT  0
#define O_EI    (O_ETOT + Bc)                 // 8
#define O_FORCE (O_EI + Bc*Nc)                // 8200
#define O_VIR   (O_FORCE + Bc*NTOT*3)         // 34312
#define OUT_TOTAL (O_VIR + Bc*9)              // 34384

typedef unsigned long long u64;

// ---------------- packed f32x2 helpers ----------------
__device__ __forceinline__ u64 pk2(float lo, float hi) {
    u64 r; asm("mov.b64 %0, {%1, %2};" : "=l"(r) : "f"(lo), "f"(hi)); return r;
}
__device__ __forceinline__ void upk2(u64 v, float& lo, float& hi) {
    asm("mov.b64 {%0, %1}, %2;" : "=f"(lo), "=f"(hi) : "l"(v));
}
__device__ __forceinline__ u64 ffma2(u64 a, u64 b, u64 c) {
    u64 d; asm("fma.rn.f32x2 %0, %1, %2, %3;" : "=l"(d) : "l"(a), "l"(b), "l"(c)); return d;
}

// ---------------- device scratch (no allocation allowed) ----------------
__device__ float  g_S    [Bc*Nc*NFEATc];   // S (B,N,16,4), already /M
__device__ float  g_feat [Bc*Nc*NFEATc];   // raw features
__device__ float  g_dfeat[Bc*Nc*NFEATc];   // dE/dfeat_raw (incl. 1/std)
__device__ double g_sum  [NTYPESc];
__device__ double g_sumsq[NTYPESc];
__device__ float  g_mu   [NTYPESc];
__device__ float  g_istd [NTYPESc];        // 1/std
__device__ float  g_W0T  [NTYPESc*Hc*NFEATc];  // [t][j][p]
__device__ float  g_W1T  [NTYPESc*Hc*Hc];      // [t][j][i]
__device__ float  g_W2T  [NTYPESc*Hc*Hc];

__device__ __forceinline__ float wsum(float v) {
    v += __shfl_xor_sync(0xffffffffu, v, 16);
    v += __shfl_xor_sync(0xffffffffu, v, 8);
    v += __shfl_xor_sync(0xffffffffu, v, 4);
    v += __shfl_xor_sync(0xffffffffu, v, 2);
    v += __shfl_xor_sync(0xffffffffu, v, 1);
    return v;
}

// packed butterfly step: 2*HALF values -> HALF, component bit taken from lane bit OFF
template<int HALF, int OFF>
__device__ __forceinline__ void bstep(float* v, int lane) {
    bool hi = (lane & OFF) != 0;
#pragma unroll
    for (int i = 0; i < HALF; i++) {
        float send = hi ? v[i] : v[i + HALF];
        float recv = __shfl_xor_sync(0xffffffffu, send, OFF);
        v[i] = (hi ? v[i + HALF] : v[i]) + recv;
    }
}

// ---------------- kernel 0: zero outputs + transpose weights -------------
__global__ void prep_kernel(float* out,
                            const float* __restrict__ W0,
                            const float* __restrict__ W1,
                            const float* __restrict__ W2) {
    int i = blockIdx.x * blockDim.x + threadIdx.x;
    if (i < OUT_TOTAL) out[i] = 0.0f;
    if (i < NTYPESc) { g_sum[i] = 0.0; g_sumsq[i] = 0.0; }
    if (i < NTYPESc*Hc*NFEATc) {
        int t = i / (Hc*NFEATc); int r = i % (Hc*NFEATc);
        int j = r / NFEATc;      int p = r % NFEATc;
        g_W0T[i] = W0[(t*NFEATc + p)*Hc + j];
    }
    if (i < NTYPESc*Hc*Hc) {
        int t = i / (Hc*Hc); int r = i % (Hc*Hc);
        int j = r / Hc;      int k = r % Hc;
        g_W1T[i] = W1[(t*Hc + k)*Hc + j];
        g_W2T[i] = W2[(t*Hc + k)*Hc + j];
    }
}

// ---------------- kernel 2: features + per-type stats --------------------
// one block per (b,n); 256 threads, one per neighbor (round-4 structure,
// fast-math geometry)
__global__ void feat_kernel(const float* __restrict__ rvec,
                            const int*   __restrict__ tmap,
                            const float* __restrict__ cparam) {
    int bn = blockIdx.x;
    int n  = bn & (Nc - 1);
    int m  = threadIdx.x;
    int ti = tmap[n];

    __shared__ __align__(16) float ct[NTYPESc*BETAc*M1c];  // [tj][k][p]
    __shared__ float S_sh[NFEATc];
    __shared__ float Sn[NFEATc];
    __shared__ float ps[8], ps2[8];

    {   // load c transposed: source index m = tj*128 + p*8 + k
        int tjl = m >> 7, rem = m & 127, p = rem >> 3, k = rem & 7;
        ct[tjl*128 + k*16 + p] = cparam[ti * (NTYPESc*M1c*BETAc) + m];
    }
    if (m < NFEATc) S_sh[m] = 0.0f;
    __syncthreads();

    const float* rv = rvec + ((long)bn * Mc + m) * 3;
    float x = rv[0], y = rv[1], z = rv[2];
    float r2 = x*x + y*y + z*z;
    bool  valid = r2 > 1e-12f;
    float rinv0 = rsqrtf(fmaxf(r2, 1e-30f));
    float rs  = valid ? r2 * rinv0 : 1.0f;
    float inv = valid ? rinv0 : 1.0f;
    float u = 2.0f*(rs - RMINc)/SPANc - 1.0f;
    u = fminf(fmaxf(u, -1.0f), 1.0f);
    float rc = fminf(fmaxf(rs, RMINc), RMAXc);
    float fc = (valid && rs < RMAXc)
             ? 0.5f*(__cosf(PI_F*(rc - RMINc)/SPANc) + 1.0f) : 0.0f;

    float T[BETAc];
    T[0] = 1.0f; T[1] = u;
#pragma unroll
    for (int k = 2; k < BETAc; k++) T[k] = 2.0f*u*T[k-1] - T[k-2];
    u64 Td[BETAc];
#pragma unroll
    for (int k = 0; k < BETAc; k++) Td[k] = pk2(T[k], T[k]);

    int tj = m >> 7;
    const u64* cp = (const u64*)(ct + tj * 128);
    float q0 = valid ? 1.0f : 0.0f;
    float qv[4]; qv[0] = q0; qv[1] = x*inv*q0; qv[2] = y*inv*q0; qv[3] = z*inv*q0;

    u64 P2[8];
#pragma unroll
    for (int pp = 0; pp < 8; pp++) P2[pp] = 0ULL;
#pragma unroll
    for (int k = 0; k < BETAc; k++)
#pragma unroll
        for (int pp = 0; pp < 8; pp++) P2[pp] = ffma2(cp[k*8 + pp], Td[k], P2[pp]);

    float gv[M1c];
#pragma unroll
    for (int pp = 0; pp < 8; pp++) {
        float a, b; upk2(P2[pp], a, b);
        gv[2*pp + 0] = a * fc;
        gv[2*pp + 1] = b * fc;
    }

    float v[NFEATc];
#pragma unroll
    for (int p = 0; p < M1c; p++) {
        v[p*4 + 0] = gv[p] * qv[0];
        v[p*4 + 1] = gv[p] * qv[1];
        v[p*4 + 2] = gv[p] * qv[2];
        v[p*4 + 3] = gv[p] * qv[3];
    }
    int lane = m & 31;
    bstep<32, 16>(v, lane);
    bstep<16,  8>(v, lane);
    bstep< 8,  4>(v, lane);
    bstep< 4,  2>(v, lane);
    bstep< 2,  1>(v, lane);
    atomicAdd(&S_sh[2*lane + 0], v[0]);
    atomicAdd(&S_sh[2*lane + 1], v[1]);
    __syncthreads();

    if (m < NFEATc) {
        float s = S_sh[m] * (1.0f / Mc);
        Sn[m] = s;
        g_S[(long)bn * NFEATc + m] = s;
    }
    __syncthreads();

    float f = 0.0f;
    if (m < NFEATc) {
        int p = m >> 2, qi = m & 3;
#pragma unroll
        for (int a = 0; a < 4; a++) f += Sn[p*4 + a] * Sn[qi*4 + a];
        g_feat[(long)bn * NFEATc + m] = f;
    }
    float fs  = wsum(f);
    float f2s = wsum(f * f);
    if (lane == 0) { ps[m >> 5] = fs; ps2[m >> 5] = f2s; }
    __syncthreads();
    if (m == 0) {
        float s = 0.0f, s2 = 0.0f;
#pragma unroll
        for (int w = 0; w < 8; w++) { s += ps[w]; s2 += ps2[w]; }
        atomicAdd(&g_sum[ti],  (double)s);
        atomicAdd(&g_sumsq[ti], (double)s2);
    }
}

// ---------------- kernel 3: finalize stats (warp-reduced counting) -------
__global__ void stats_kernel(const int* __restrict__ tmap) {
    __shared__ float wcnt[8];
    int tid = threadIdx.x;
    float c0 = 0.0f;
    for (int i = tid; i < Nc; i += 256) c0 += (tmap[i] == 0) ? 1.0f : 0.0f;
    c0 = wsum(c0);
    if ((tid & 31) == 0) wcnt[tid >> 5] = c0;
    __syncthreads();
    if (tid == 0) {
        float n0 = 0.0f;
#pragma unroll
        for (int w = 0; w < 8; w++) n0 += wcnt[w];
        int cnt[NTYPESc];
        cnt[0] = (int)(n0 + 0.5f);
        cnt[1] = Nc - cnt[0];
        for (int t = 0; t < NTYPESc; t++) {
            double c   = (double)cnt[t] * Bc * NFEATc;
            double mu  = g_sum[t] / c;
            double var = (g_sumsq[t] - g_sum[t]*g_sum[t]/c) / (c - 1.0);
            g_mu[t]   = (float)mu;
            g_istd[t] = (float)(1.0 / sqrt(var));
        }
    }
}

// ---------------- kernel 4: MLP fwd+bwd, warp-per-4-atoms, 2-warp blocks --
// acc layout: acc2[o*2 + h], h=0 -> atoms(0,1), h=1 -> atoms(2,3)
__device__ __forceinline__ void fma8x2(u64 (&z)[8], float4 wv, float4 xv) {
    u64 x01 = pk2(xv.x, xv.y);
    u64 x23 = pk2(xv.z, xv.w);
    u64 wd;
    wd = pk2(wv.x, wv.x); z[0] = ffma2(wd, x01, z[0]); z[1] = ffma2(wd, x23, z[1]);
    wd = pk2(wv.y, wv.y); z[2] = ffma2(wd, x01, z[2]); z[3] = ffma2(wd, x23, z[3]);
    wd = pk2(wv.z, wv.z); z[4] = ffma2(wd, x01, z[4]); z[5] = ffma2(wd, x23, z[5]);
    wd = pk2(wv.w, wv.w); z[6] = ffma2(wd, x01, z[6]); z[7] = ffma2(wd, x23, z[7]);
}

#define MLP_WARPS 2
#define APW 4
__global__ void __launch_bounds__(64) mlp_kernel(
        const int* __restrict__ tmap,
        const float* __restrict__ W0, const float* __restrict__ b0,
        const float* __restrict__ W1, const float* __restrict__ b1,
        const float* __restrict__ W2, const float* __restrict__ b2,
        const float* __restrict__ Wout, const float* __restrict__ bout,
        float* __restrict__ outEi, float* __restrict__ outEtot) {
    __shared__ float4 bufA[MLP_WARPS][Hc];
    __shared__ float4 bufB[MLP_WARPS][Hc];

    const int w   = threadIdx.x >> 5;
    const int ln  = threadIdx.x & 31;
    const int bn0 = (blockIdx.x * MLP_WARPS + w) * APW;
    const int n0  = bn0 & (Nc - 1);
    const int b   = bn0 >> 10;
    const int t   = tmap[n0];          // 4 consecutive atoms share type (sorted tmap)
    const float mu = g_mu[t], istd = g_istd[t];

    float*        Af = (float*)bufA[w];
    const float4* A4 = bufA[w];
    const float4* B4 = bufB[w];

    // load normalized features, layout [p][atom]
#pragma unroll
    for (int k = 0; k < 8; k++) {
        int idx = k * 32 + ln;
        int p = idx >> 2, a = idx & 3;
        Af[idx] = (g_feat[(size_t)(bn0 + a) * NFEATc + p] - mu) * istd;
    }
    __syncwarp();

    const float4* W0f  = (const float4*)(W0    + (size_t)t * NFEATc * Hc);
    const float4* W1f  = (const float4*)(W1    + (size_t)t * Hc * Hc);
    const float4* W2f  = (const float4*)(W2    + (size_t)t * Hc * Hc);
    const float4* W1Tf = (const float4*)(g_W1T + (size_t)t * Hc * Hc);
    const float4* W2Tf = (const float4*)(g_W2T + (size_t)t * Hc * Hc);
    const float2* W0T2 = (const float2*)(g_W0T + (size_t)t * Hc * NFEATc);

    u64 acc2[8];
    float a0r[16], a1r[16], a2r[16], h1r[16];

    // ---- layer 0: 64 -> 128 ----
    {
        float4 bb = ((const float4*)(b0 + t * Hc))[ln];
        acc2[0] = acc2[1] = pk2(bb.x, bb.x);
        acc2[2] = acc2[3] = pk2(bb.y, bb.y);
        acc2[4] = acc2[5] = pk2(bb.z, bb.z);
        acc2[6] = acc2[7] = pk2(bb.w, bb.w);
    }
#pragma unroll 4
    for (int p = 0; p < NFEATc; p++) fma8x2(acc2, W0f[p*32 + ln], A4[p]);
#pragma unroll
    for (int o = 0; o < 4; o++) {
        float u0_, u1_, u2_, u3_;
        upk2(acc2[o*2],   u0_, u1_);
        upk2(acc2[o*2+1], u2_, u3_);
        a0r[o*4+0] = tanhf(u0_); a0r[o*4+1] = tanhf(u1_);
        a0r[o*4+2] = tanhf(u2_); a0r[o*4+3] = tanhf(u3_);
    }
#pragma unroll
    for (int c = 0; c < 4; c++)
        bufB[w][4*ln + c] = make_float4(a0r[c*4+0], a0r[c*4+1], a0r[c*4+2], a0r[c*4+3]);
    __syncwarp();

    // ---- layer 1 ----
    {
        float4 bb = ((const float4*)(b1 + t * Hc))[ln];
        acc2[0] = acc2[1] = pk2(bb.x, bb.x);
        acc2[2] = acc2[3] = pk2(bb.y, bb.y);
        acc2[4] = acc2[5] = pk2(bb.z, bb.z);
        acc2[6] = acc2[7] = pk2(bb.w, bb.w);
    }
#pragma unroll 4
    for (int p = 0; p < Hc; p++) fma8x2(acc2, W1f[p*32 + ln], B4[p]);
#pragma unroll
    for (int o = 0; o < 4; o++) {
        float u0_, u1_, u2_, u3_;
        upk2(acc2[o*2],   u0_, u1_);
        upk2(acc2[o*2+1], u2_, u3_);
        a1r[o*4+0] = tanhf(u0_); a1r[o*4+1] = tanhf(u1_);
        a1r[o*4+2] = tanhf(u2_); a1r[o*4+3] = tanhf(u3_);
    }
#pragma unroll
    for (int i = 0; i < 16; i++) h1r[i] = a1r[i] + a0r[i];
#pragma unroll
    for (int c = 0; c < 4; c++)
        bufA[w][4*ln + c] = make_float4(h1r[c*4+0], h1r[c*4+1], h1r[c*4+2], h1r[c*4+3]);
    __syncwarp();

    // ---- layer 2 ----
    {
        float4 bb = ((const float4*)(b2 + t * Hc))[ln];
        acc2[0] = acc2[1] = pk2(bb.x, bb.x);
        acc2[2] = acc2[3] = pk2(bb.y, bb.y);
        acc2[4] = acc2[5] = pk2(bb.z, bb.z);
        acc2[6] = acc2[7] = pk2(bb.w, bb.w);
    }
#pragma unroll 4
    for (int p = 0; p < Hc; p++) fma8x2(acc2, W2f[p*32 + ln], A4[p]);
#pragma unroll
    for (int o = 0; o < 4; o++) {
        float u0_, u1_, u2_, u3_;
        upk2(acc2[o*2],   u0_, u1_);
        upk2(acc2[o*2+1], u2_, u3_);
        a2r[o*4+0] = tanhf(u0_); a2r[o*4+1] = tanhf(u1_);
        a2r[o*4+2] = tanhf(u2_); a2r[o*4+3] = tanhf(u3_);
    }

    // ---- energy ----
    float4 wo = ((const float4*)(Wout + t * Hc))[ln];
    float e0, e1, e2, e3;
    {
        float h2[16];
#pragma unroll
        for (int i = 0; i < 16; i++) h2[i] = a2r[i] + h1r[i];
        e0 = wo.x*h2[0] + wo.y*h2[4] + wo.z*h2[ 8] + wo.w*h2[12];
        e1 = wo.x*h2[1] + wo.y*h2[5] + wo.z*h2[ 9] + wo.w*h2[13];
        e2 = wo.x*h2[2] + wo.y*h2[6] + wo.z*h2[10] + wo.w*h2[14];
        e3 = wo.x*h2[3] + wo.y*h2[7] + wo.z*h2[11] + wo.w*h2[15];
    }
    e0 = wsum(e0); e1 = wsum(e1); e2 = wsum(e2); e3 = wsum(e3);
    float bo = bout[t];
    if (ln < 4) {
        float myE = (ln == 0) ? e0 : (ln == 1) ? e1 : (ln == 2) ? e2 : e3;
        outEi[bn0 + ln] = myE + bo;
    }
    if (ln == 0) atomicAdd(&outEtot[b], e0 + e1 + e2 + e3 + 4.0f * bo);

    // ---- backward ----
    // v2 = wo(c) * (1 - a2^2) -> B
#pragma unroll
    for (int c = 0; c < 4; c++) {
        float wc = (c == 0) ? wo.x : (c == 1) ? wo.y : (c == 2) ? wo.z : wo.w;
        bufB[w][4*ln + c] = make_float4(wc * (1.0f - a2r[c*4+0]*a2r[c*4+0]),
                                        wc * (1.0f - a2r[c*4+1]*a2r[c*4+1]),
                                        wc * (1.0f - a2r[c*4+2]*a2r[c*4+2]),
                                        wc * (1.0f - a2r[c*4+3]*a2r[c*4+3]));
    }
    __syncwarp();

    u64 dh2[8];   // packed dE/dh accumulators, same layout as acc2
    dh2[0] = dh2[1] = pk2(wo.x, wo.x);
    dh2[2] = dh2[3] = pk2(wo.y, wo.y);
    dh2[4] = dh2[5] = pk2(wo.z, wo.z);
    dh2[6] = dh2[7] = pk2(wo.w, wo.w);
#pragma unroll 4
    for (int j = 0; j < Hc; j++) fma8x2(dh2, W2Tf[j*32 + ln], B4[j]);

    // v1 = dh1 * (1 - a1^2) -> A
#pragma unroll
    for (int o = 0; o < 4; o++) {
        float d0, d1, d2, d3;
        upk2(dh2[o*2],   d0, d1);
        upk2(dh2[o*2+1], d2, d3);
        bufA[w][4*ln + o] = make_float4(d0 * (1.0f - a1r[o*4+0]*a1r[o*4+0]),
                                        d1 * (1.0f - a1r[o*4+1]*a1r[o*4+1]),
                                        d2 * (1.0f - a1r[o*4+2]*a1r[o*4+2]),
                                        d3 * (1.0f - a1r[o*4+3]*a1r[o*4+3]));
    }
    __syncwarp();

#pragma unroll 4
    for (int j = 0; j < Hc; j++) fma8x2(dh2, W1Tf[j*32 + ln], A4[j]);

    // v0 = dh0 * (1 - a0^2) -> B
#pragma unroll
    for (int o = 0; o < 4; o++) {
        float d0, d1, d2, d3;
        upk2(dh2[o*2],   d0, d1);
        upk2(dh2[o*2+1], d2, d3);
        bufB[w][4*ln + o] = make_float4(d0 * (1.0f - a0r[o*4+0]*a0r[o*4+0]),
                                        d1 * (1.0f - a0r[o*4+1]*a0r[o*4+1]),
                                        d2 * (1.0f - a0r[o*4+2]*a0r[o*4+2]),
                                        d3 * (1.0f - a0r[o*4+3]*a0r[o*4+3]));
    }
    __syncwarp();

    // dx_p = sum_j W0T[j][p] * v0[j], thread owns p = 2ln, 2ln+1
    u64 dx0p[2] = {0ULL, 0ULL}, dx1p[2] = {0ULL, 0ULL};
#pragma unroll 4
    for (int j = 0; j < Hc; j++) {
        float2 w2 = W0T2[j*32 + ln];
        float4 vv = B4[j];
        u64 v01 = pk2(vv.x, vv.y);
        u64 v23 = pk2(vv.z, vv.w);
        u64 wd0 = pk2(w2.x, w2.x);
        u64 wd1 = pk2(w2.y, w2.y);
        dx0p[0] = ffma2(wd0, v01, dx0p[0]); dx0p[1] = ffma2(wd0, v23, dx0p[1]);
        dx1p[0] = ffma2(wd1, v01, dx1p[0]); dx1p[1] = ffma2(wd1, v23, dx1p[1]);
    }
    float dx0[4], dx1[4];
    upk2(dx0p[0], dx0[0], dx0[1]); upk2(dx0p[1], dx0[2], dx0[3]);
    upk2(dx1p[0], dx1[0], dx1[1]); upk2(dx1p[1], dx1[2], dx1[3]);
#pragma unroll
    for (int a = 0; a < 4; a++) {
        ((float2*)g_dfeat)[(size_t)(bn0 + a) * (NFEATc/2) + ln] =
            make_float2(dx0[a] * istd, dx1[a] * istd);
    }
}

// ---------------- kernel 5: gradient w.r.t. rvec, forces, virial ----------
__global__ void grad_kernel(const float* __restrict__ rvec,
                            const int*   __restrict__ tmap,
                            const float* __restrict__ cparam,
                            const int*   __restrict__ list_neigh,
                            float* __restrict__ Force,
                            float* __restrict__ Virial) {
    int bn = blockIdx.x;
    int n  = bn & (Nc - 1);
    int b  = bn >> 10;
    int m  = threadIdx.x;
    int ti = tmap[n];

    __shared__ __align__(16) float ct[NTYPESc*BETAc*M1c];  // [tj][k][p]
    __shared__ float dfs[NFEATc], Ss[NFEATc];
    __shared__ __align__(16) float dsT[4*M1c];             // [a][p]
    __shared__ float acc[12];

    {
        int tjl = m >> 7, rem = m & 127, p = rem >> 3, k = rem & 7;
        ct[tjl*128 + k*16 + p] = cparam[ti * (NTYPESc*M1c*BETAc) + m];
    }
    if (m < NFEATc) {
        dfs[m] = g_dfeat[(long)bn*NFEATc + m];
        Ss[m]  = g_S[(long)bn*NFEATc + m];
    }
    if (m < 12) acc[m] = 0.0f;
    __syncthreads();

    if (m < NFEATc) {
        int r = m >> 2, a = m & 3;
        float v = 0.0f;
#pragma unroll
        for (int q = 0; q < 4; q++) v += dfs[r*4 + q] * Ss[q*4 + a];
        if (r < 4) {
#pragma unroll
            for (int p = 0; p < M1c; p++) v += dfs[p*4 + r] * Ss[p*4 + a];
        }
        dsT[a*M1c + r] = v;
    }
    __syncthreads();

    const float* rv = rvec + ((long)bn * Mc + m) * 3;
    float x = rv[0], y = rv[1], z = rv[2];
    float r2 = x*x + y*y + z*z;
    bool  valid = r2 > 1e-12f;
    float rinv0 = rsqrtf(fmaxf(r2, 1e-30f));
    float rs  = valid ? r2 * rinv0 : 1.0f;
    float inv = valid ? rinv0 : 1.0f;
    float ux = x*inv, uy = y*inv, uz = z*inv;

    float u0 = 2.0f*(rs - RMINc)/SPANc - 1.0f;
    bool  uin = (u0 > -1.0f) && (u0 < 1.0f);
    float u = fminf(fmaxf(u0, -1.0f), 1.0f);
    float rc = fminf(fmaxf(rs, RMINc), RMAXc);
    float arg = PI_F*(rc - RMINc)/SPANc;
    float fc = (valid && rs < RMAXc) ? 0.5f*(__cosf(arg) + 1.0f) : 0.0f;
    float dfc_dr = (valid && rs < RMAXc && rs > RMINc)
                 ? -0.5f*PI_F/SPANc*__sinf(arg) : 0.0f;
    float du_dr  = uin ? 2.0f/SPANc : 0.0f;

    float T[BETAc], D[BETAc];
    T[0] = 1.0f; T[1] = u; D[0] = 0.0f; D[1] = 1.0f;
#pragma unroll
    for (int k = 2; k < BETAc; k++) {
        T[k] = 2.0f*u*T[k-1] - T[k-2];
        D[k] = 2.0f*T[k-1] + 2.0f*u*D[k-1] - D[k-2];
    }
    u64 Td[BETAc], Dd[BETAc];
#pragma unroll
    for (int k = 0; k < BETAc; k++) { Td[k] = pk2(T[k], T[k]); Dd[k] = pk2(D[k], D[k]); }

    int tj = m >> 7;
    const u64* cp  = (const u64*)(ct + tj * 128);
    const u64* ds0 = (const u64*)dsT;
    float q0 = valid ? 1.0f : 0.0f;
    float qv[4]; qv[0] = q0; qv[1] = ux*q0; qv[2] = uy*q0; qv[3] = uz*q0;

    u64 P2[8], Pd2[8];
#pragma unroll
    for (int pp = 0; pp < 8; pp++) { P2[pp] = 0ULL; Pd2[pp] = 0ULL; }
#pragma unroll
    for (int k = 0; k < BETAc; k++) {
#pragma unroll
        for (int pp = 0; pp < 8; pp++) {
            u64 c2 = cp[k*8 + pp];
            P2[pp]  = ffma2(c2, Td[k], P2[pp]);
            Pd2[pp] = ffma2(c2, Dd[k], Pd2[pp]);
        }
    }

    u64 dg2[8];
#pragma unroll
    for (int pp = 0; pp < 8; pp++) dg2[pp] = 0ULL;
#pragma unroll
    for (int a = 0; a < 4; a++) {
        u64 qd = pk2(qv[a], qv[a]);
#pragma unroll
        for (int pp = 0; pp < 8; pp++) dg2[pp] = ffma2(ds0[a*8 + pp], qd, dg2[pp]);
    }

    u64 f2 = 0ULL, up2 = 0ULL, x2 = 0ULL, y2 = 0ULL, z2 = 0ULL;
#pragma unroll
    for (int pp = 0; pp < 8; pp++) {
        f2  = ffma2(dg2[pp], P2[pp],  f2);
        up2 = ffma2(dg2[pp], Pd2[pp], up2);
        x2  = ffma2(ds0[ 8 + pp], P2[pp], x2);
        y2  = ffma2(ds0[16 + pp], P2[pp], y2);
        z2  = ffma2(ds0[24 + pp], P2[pp], z2);
    }
    const float invM = 1.0f / Mc;
    float lo_, hi_;
    upk2(f2,  lo_, hi_); float dfc = (lo_ + hi_) * invM;
    upk2(up2, lo_, hi_); float duP = (lo_ + hi_) * invM;
    upk2(x2,  lo_, hi_); float dux = (lo_ + hi_) * invM * fc * q0;
    upk2(y2,  lo_, hi_); float duy = (lo_ + hi_) * invM * fc * q0;
    upk2(z2,  lo_, hi_); float duz = (lo_ + hi_) * invM * fc * q0;

    float du  = fc * duP;
    float drs = dfc * dfc_dr + du * du_dr;
    float dot = dux*ux + duy*uy + duz*uz;

    float fx = 0.0f, fy = 0.0f, fz = 0.0f;
    if (valid) {
        fx = drs*ux + (dux - dot*ux)*inv;
        fy = drs*uy + (duy - dot*uy)*inv;
        fz = drs*uz + (duz - dot*uz)*inv;
    }

    int nb = list_neigh[(long)bn * Mc + m];
    if (nb > 0) {
        long fj = ((long)b * NTOT + (nb - 1)) * 3;
        atomicAdd(&Force[fj + 0], -fx);
        atomicAdd(&Force[fj + 1], -fy);
        atomicAdd(&Force[fj + 2], -fz);
    }

    // center force + virial: packed butterfly over 16 components + final
    // parity add (OFF=1) so every lane holds the FULL warp sum of
    // component ((lane>>1)&15).
    int lane = m & 31;
    float vals[16];
    vals[0] = fx;   vals[1] = fy;   vals[2] = fz;
    vals[3]  = x*fx; vals[4]  = x*fy; vals[5]  = x*fz;
    vals[6]  = y*fx; vals[7]  = y*fy; vals[8]  = y*fz;
    vals[9]  = z*fx; vals[10] = z*fy; vals[11] = z*fz;
    vals[12] = vals[13] = vals[14] = vals[15] = 0.0f;
    bstep<8, 16>(vals, lane);
    bstep<4,  8>(vals, lane);
    bstep<2,  4>(vals, lane);
    bstep<1,  2>(vals, lane);
    vals[0] += __shfl_xor_sync(0xffffffffu, vals[0], 1);
    if ((lane & 1) == 0) {
        int c = (lane >> 1) & 15;
        if (c < 12) atomicAdd(&acc[c], vals[0]);
    }
    __syncthreads();
    if (m < 3)  atomicAdd(&Force[((long)b*NTOT + n)*3 + m], acc[m]);
    if (m >= 3 && m < 12) atomicAdd(&Virial[b*9 + (m - 3)], -acc[m]);
}

// ---------------- launch ---------------------------------------------------
extern "C" void kernel_launch(void* const* d_in, const int* in_sizes, int n_in,
                              void* d_out, int out_size) {
    const int*   list_neigh = (const int*)  d_in[0];
    const int*   tmap       = (const int*)  d_in[1];
    const float* rvec       = (const float*)d_in[2];
    const float* cparam     = (const float*)d_in[3];
    const float* W0         = (const float*)d_in[4];
    const float* b0         = (const float*)d_in[5];
    const float* W1         = (const float*)d_in[6];
    const float* b1         = (const float*)d_in[7];
    const float* W2         = (const float*)d_in[8];
    const float* b2         = (const float*)d_in[9];
    const float* Wout       = (const float*)d_in[10];
    const float* bout       = (const float*)d_in[11];

    float* out      = (float*)d_out;
    float* outEtot  = out + O_ETOT;
    float* outEi    = out + O_EI;
    float* outForce = out + O_FORCE;
    float* outVir   = out + O_VIR;

    prep_kernel<<<(OUT_TOTAL + 255) / 256, 256>>>(out, W0, W1, W2);
    feat_kernel<<<Bc*Nc, 256>>>(rvec, tmap, cparam);
    stats_kernel<<<1, 256>>>(tmap);
    mlp_kernel<<<Bc*Nc / (MLP_WARPS*APW), MLP_WARPS*32>>>(tmap, W0, b0, W1, b1,
                                                          W2, b2, Wout, bout,
                                                          outEi, outEtot);
    grad_kernel<<<Bc*Nc, 256>>>(rvec, tmap, cparam, list_neigh, outForce, outVir);
}